// round 1
// baseline (speedup 1.0000x reference)
#include <cuda_runtime.h>
#include <math.h>

#define BB 4
#define DIM 192
#define C3 576
#define HF 256
#define WF 256
#define HP 128
#define WP 128
#define NPX 16384
#define NHEADS 6
#define CPH 32

// scratch (device globals: allocation-free)
__device__ float g_P[BB * C3 * HP * WP];    // pooled qkv   (151 MB)
__device__ float g_D[BB * C3 * HP * WP];    // after dwconv (151 MB)
__device__ float g_low[BB * DIM * NPX];     // gelu(out) low-res (50 MB)
__device__ float g_G[BB * NHEADS * CPH * CPH];
__device__ float g_A[BB * NHEADS * CPH * CPH];
__device__ float g_sq[BB * NHEADS * CPH];
__device__ float g_sk[BB * NHEADS * CPH];

__device__ __forceinline__ float2 ffma2(float2 a, float2 b, float2 c) {
    float2 d;
    asm("fma.rn.f32x2 %0, %1, %2, %3;"
        : "=l"(*(unsigned long long*)&d)
        : "l"(*(unsigned long long*)&a),
          "l"(*(unsigned long long*)&b),
          "l"(*(unsigned long long*)&c));
    return d;
}

// ---------------------------------------------------------------------------
// K1: fused 1x1 qkv conv + 2x2 maxpool.
// Block tile: 64 co x 32 pooled px (= 2 full-res rows x 64 cols).
// Thread: 8 co x 1 pooled quad (4 full-res px packed as 2 x f32x2).
// ---------------------------------------------------------------------------
__global__ __launch_bounds__(256) void k1_qkv_pool(const float* __restrict__ x,
                                                   const float* __restrict__ w) {
    int jt = blockIdx.x;              // 0..3  (32 pooled cols each)
    int i  = blockIdx.y;              // pooled row 0..127
    int b  = blockIdx.z / 9;
    int cot = blockIdx.z % 9;
    int tid = threadIdx.x;
    int lpx = tid & 31;               // pooled col within tile
    int cog = tid >> 5;               // 0..7 (8 co each)

    __shared__ __align__(16) float xs[16][2][64];   // 8 KB
    __shared__ __align__(16) float ws[16][128];     // 8 KB, duplicated pairs {w,w}

    const float* xb = x + (size_t)b * DIM * (HF * WF);
    int col0 = jt * 64;
    int row0 = 2 * i;
    int cobase = cot * 64;

    float2 acc[8][2];
#pragma unroll
    for (int j = 0; j < 8; j++) {
        acc[j][0] = make_float2(0.f, 0.f);
        acc[j][1] = make_float2(0.f, 0.f);
    }

    for (int k0 = 0; k0 < DIM; k0 += 16) {
        // load x tile: 16 k x 2 rows x 64 cols
#pragma unroll
        for (int rep = 0; rep < 2; rep++) {
            int l = tid * 8 + rep * 4;
            int c = l & 63, r = (l >> 6) & 1, kk = l >> 7;
            float4 v = *reinterpret_cast<const float4*>(
                &xb[(size_t)(k0 + kk) * (HF * WF) + (size_t)(row0 + r) * WF + col0 + c]);
            *reinterpret_cast<float4*>(&xs[kk][r][c]) = v;
        }
        // load w tile transposed + duplicated: ws[k][2*co] = ws[k][2*co+1] = w[co][k]
        {
            int co = tid & 63, kq = tid >> 6;
            float4 v = *reinterpret_cast<const float4*>(&w[(size_t)(cobase + co) * DIM + k0 + kq * 4]);
            *reinterpret_cast<float2*>(&ws[kq * 4 + 0][2 * co]) = make_float2(v.x, v.x);
            *reinterpret_cast<float2*>(&ws[kq * 4 + 1][2 * co]) = make_float2(v.y, v.y);
            *reinterpret_cast<float2*>(&ws[kq * 4 + 2][2 * co]) = make_float2(v.z, v.z);
            *reinterpret_cast<float2*>(&ws[kq * 4 + 3][2 * co]) = make_float2(v.w, v.w);
        }
        __syncthreads();
#pragma unroll
        for (int kk = 0; kk < 16; kk++) {
            float2 x0 = *reinterpret_cast<const float2*>(&xs[kk][0][lpx * 2]);
            float2 x1 = *reinterpret_cast<const float2*>(&xs[kk][1][lpx * 2]);
#pragma unroll
            for (int m = 0; m < 4; m++) {
                float4 wp = *reinterpret_cast<const float4*>(&ws[kk][cog * 16 + m * 4]);
                float2 wd0 = make_float2(wp.x, wp.y);   // {w_{2m},   w_{2m}}
                float2 wd1 = make_float2(wp.z, wp.w);   // {w_{2m+1}, w_{2m+1}}
                acc[2 * m + 0][0] = ffma2(x0, wd0, acc[2 * m + 0][0]);
                acc[2 * m + 0][1] = ffma2(x1, wd0, acc[2 * m + 0][1]);
                acc[2 * m + 1][0] = ffma2(x0, wd1, acc[2 * m + 1][0]);
                acc[2 * m + 1][1] = ffma2(x1, wd1, acc[2 * m + 1][1]);
            }
        }
        __syncthreads();
    }
#pragma unroll
    for (int j = 0; j < 8; j++) {
        float m = fmaxf(fmaxf(acc[j][0].x, acc[j][0].y), fmaxf(acc[j][1].x, acc[j][1].y));
        int co = cobase + cog * 8 + j;
        g_P[((size_t)(b * C3 + co) * HP + i) * WP + jt * 32 + lpx] = m;
    }
}

// ---------------------------------------------------------------------------
// K2: depthwise 3x3, SAME (zero pad), stride 1, on pooled grid.
// ---------------------------------------------------------------------------
__global__ void k2_dw(const float* __restrict__ dw) {
    int i = blockIdx.x, c = blockIdx.y, b = blockIdx.z;
    int j = threadIdx.x;  // 128
    __shared__ float s[3][130];
    const float* base = g_P + (size_t)(b * C3 + c) * HP * WP;
#pragma unroll
    for (int r = 0; r < 3; r++) {
        int ri = i + r - 1;
        s[r][j + 1] = (ri >= 0 && ri < HP) ? base[(size_t)ri * WP + j] : 0.f;
        if (j == 0) { s[r][0] = 0.f; s[r][129] = 0.f; }
    }
    __syncthreads();
    float acc = 0.f;
#pragma unroll
    for (int r = 0; r < 3; r++)
#pragma unroll
        for (int t = 0; t < 3; t++)
            acc = fmaf(dw[c * 9 + r * 3 + t], s[r][j + t], acc);
    g_D[((size_t)(b * C3 + c) * HP + i) * WP + j] = acc;
}

// ---------------------------------------------------------------------------
// K3: zero-init for accumulators
// ---------------------------------------------------------------------------
__global__ void k_init() {
    int idx = blockIdx.x * blockDim.x + threadIdx.x;
    if (idx < BB * NHEADS * CPH * CPH) g_G[idx] = 0.f;
    if (idx < BB * NHEADS * CPH) { g_sq[idx] = 0.f; g_sk[idx] = 0.f; }
}

// ---------------------------------------------------------------------------
// K4: gram matrix G = q @ k^T (raw) + per-row sum-of-squares for q, k.
// grid (16 n-splits, 6 heads, 4 batch); each block reduces 1024 pixels.
// ---------------------------------------------------------------------------
__global__ __launch_bounds__(256) void k4_gram() {
    int s = blockIdx.x, h = blockIdx.y, b = blockIdx.z;
    int tid = threadIdx.x;
    __shared__ float qs[32][65];
    __shared__ float ks_[32][65];
    const float* qb = g_D + (size_t)(b * C3 + h * CPH) * NPX;
    const float* kb = g_D + (size_t)(b * C3 + DIM + h * CPH) * NPX;
    int row = tid >> 3;
    int cc = (tid & 7) * 8;
    int c = tid >> 3;
    int dbase = (tid & 7) * 4;
    float acc[4] = {0.f, 0.f, 0.f, 0.f};
    float sloc = 0.f;
    int n0 = s * 1024;
    for (int c0 = n0; c0 < n0 + 1024; c0 += 64) {
        float4 q0 = *reinterpret_cast<const float4*>(&qb[(size_t)row * NPX + c0 + cc]);
        float4 q1 = *reinterpret_cast<const float4*>(&qb[(size_t)row * NPX + c0 + cc + 4]);
        float4 k0v = *reinterpret_cast<const float4*>(&kb[(size_t)row * NPX + c0 + cc]);
        float4 k1v = *reinterpret_cast<const float4*>(&kb[(size_t)row * NPX + c0 + cc + 4]);
        qs[row][cc + 0] = q0.x; qs[row][cc + 1] = q0.y; qs[row][cc + 2] = q0.z; qs[row][cc + 3] = q0.w;
        qs[row][cc + 4] = q1.x; qs[row][cc + 5] = q1.y; qs[row][cc + 6] = q1.z; qs[row][cc + 7] = q1.w;
        ks_[row][cc + 0] = k0v.x; ks_[row][cc + 1] = k0v.y; ks_[row][cc + 2] = k0v.z; ks_[row][cc + 3] = k0v.w;
        ks_[row][cc + 4] = k1v.x; ks_[row][cc + 5] = k1v.y; ks_[row][cc + 6] = k1v.z; ks_[row][cc + 7] = k1v.w;
        __syncthreads();
#pragma unroll 4
        for (int kk = 0; kk < 64; kk++) {
            float qv = qs[c][kk];
#pragma unroll
            for (int j = 0; j < 4; j++) acc[j] = fmaf(qv, ks_[dbase + j][kk], acc[j]);
        }
        if (tid < 32) {
#pragma unroll 4
            for (int kk = 0; kk < 64; kk++) sloc = fmaf(qs[tid][kk], qs[tid][kk], sloc);
        } else if (tid < 64) {
#pragma unroll 4
            for (int kk = 0; kk < 64; kk++) sloc = fmaf(ks_[tid - 32][kk], ks_[tid - 32][kk], sloc);
        }
        __syncthreads();
    }
    int bh = b * NHEADS + h;
#pragma unroll
    for (int j = 0; j < 4; j++)
        atomicAdd(&g_G[((size_t)bh * CPH + c) * CPH + dbase + j], acc[j]);
    if (tid < 32) atomicAdd(&g_sq[bh * CPH + tid], sloc);
    else if (tid < 64) atomicAdd(&g_sk[bh * CPH + tid - 32], sloc);
}

// ---------------------------------------------------------------------------
// K5: normalize gram -> attn, 4 top-k masked softmaxes fused into combined A.
// rank = exact torch.topk semantics (ties broken by lower index).
// ---------------------------------------------------------------------------
__global__ void k5_softmax(const float* __restrict__ temp,
                           const float* __restrict__ a1p, const float* __restrict__ a2p,
                           const float* __restrict__ a3p, const float* __restrict__ a4p) {
    int bh = blockIdx.x;
    int h = bh % NHEADS;
    int tid = threadIdx.x;
    int warp = tid >> 5, d = tid & 31;
    float t = temp[h];
    float A1 = *a1p, A2 = *a2p, A3 = *a3p, A4 = *a4p;
    float rk = 1.f / fmaxf(sqrtf(g_sk[bh * CPH + d]), 1e-12f);
    for (int it = 0; it < 4; it++) {
        int c = warp * 4 + it;
        float rq = 1.f / fmaxf(sqrtf(g_sq[bh * CPH + c]), 1e-12f);
        float v = g_G[((size_t)bh * CPH + c) * CPH + d] * rq * rk * t;
        int rank = 0;
#pragma unroll
        for (int j = 0; j < 32; j++) {
            float vj = __shfl_sync(0xffffffffu, v, j);
            rank += (vj > v) || (vj == v && j < d);
        }
        float vmax = v;
#pragma unroll
        for (int o = 16; o; o >>= 1) vmax = fmaxf(vmax, __shfl_xor_sync(0xffffffffu, vmax, o));
        float e = expf(v - vmax);
        float e1 = rank < 16 ? e : 0.f;
        float e2 = rank < 21 ? e : 0.f;
        float e3 = rank < 24 ? e : 0.f;
        float e4 = rank < 25 ? e : 0.f;
#pragma unroll
        for (int o = 16; o; o >>= 1) {
            e1 += __shfl_xor_sync(0xffffffffu, e1, o);
            e2 += __shfl_xor_sync(0xffffffffu, e2, o);
            e3 += __shfl_xor_sync(0xffffffffu, e3, o);
            e4 += __shfl_xor_sync(0xffffffffu, e4, o);
        }
        float wgt = (rank < 16 ? A1 / e1 : 0.f) + (rank < 21 ? A2 / e2 : 0.f)
                  + (rank < 24 ? A3 / e3 : 0.f) + (rank < 25 ? A4 / e4 : 0.f);
        g_A[((size_t)bh * CPH + c) * CPH + d] = e * wgt;
    }
}

// ---------------------------------------------------------------------------
// K6: out_low = A @ v, then exact GELU. One pixel per thread, A in smem.
// ---------------------------------------------------------------------------
__global__ __launch_bounds__(256) void k6_apply() {
    int bh = blockIdx.y;
    int b = bh / NHEADS, h = bh % NHEADS;
    int tid = threadIdx.x;
    __shared__ float As[32][32];
    reinterpret_cast<float4*>(&As[0][0])[tid] =
        reinterpret_cast<const float4*>(&g_A[(size_t)bh * 1024])[tid];
    __syncthreads();
    int px = blockIdx.x * 256 + tid;
    const float* vb = g_D + (size_t)(b * C3 + 2 * DIM + h * CPH) * NPX + px;
    float acc[32];
#pragma unroll
    for (int c = 0; c < 32; c++) acc[c] = 0.f;
#pragma unroll 4
    for (int d = 0; d < 32; d++) {
        float vd = vb[(size_t)d * NPX];
#pragma unroll
        for (int c = 0; c < 32; c++) acc[c] = fmaf(As[c][d], vd, acc[c]);
    }
    float* ob = g_low + (size_t)(b * DIM + h * CPH) * NPX + px;
#pragma unroll
    for (int c = 0; c < 32; c++) {
        float xg = acc[c];
        ob[(size_t)c * NPX] = 0.5f * xg * (1.f + erff(xg * 0.70710678118654752f));
    }
}

// ---------------------------------------------------------------------------
// K7: proj 1x1 conv at LOW-res (commutes with nearest upsample) + 4-way
// duplicate epilogue into full-res d_out. Same f32x2 GEMM structure as K1.
// ---------------------------------------------------------------------------
__global__ __launch_bounds__(256) void k7_proj(const float* __restrict__ w,
                                               float* __restrict__ out) {
    int pxt = blockIdx.x, cot = blockIdx.y, b = blockIdx.z;
    int tid = threadIdx.x;
    int lpx = tid & 31;   // 4 low-res px each
    int cog = tid >> 5;   // 8 co each
    __shared__ __align__(16) float xs[16][128];
    __shared__ __align__(16) float ws[16][128];
    const float* xb = g_low + (size_t)b * DIM * NPX;
    int px0 = pxt * 128;
    int cobase = cot * 64;
    float2 acc[8][2];
#pragma unroll
    for (int j = 0; j < 8; j++) {
        acc[j][0] = make_float2(0.f, 0.f);
        acc[j][1] = make_float2(0.f, 0.f);
    }
    for (int k0 = 0; k0 < DIM; k0 += 16) {
#pragma unroll
        for (int rep = 0; rep < 2; rep++) {
            int l = tid * 8 + rep * 4;
            int c = l & 127, kk = l >> 7;
            *reinterpret_cast<float4*>(&xs[kk][c]) =
                *reinterpret_cast<const float4*>(&xb[(size_t)(k0 + kk) * NPX + px0 + c]);
        }
        {
            int co = tid & 63, kq = tid >> 6;
            float4 v = *reinterpret_cast<const float4*>(&w[(size_t)(cobase + co) * DIM + k0 + kq * 4]);
            *reinterpret_cast<float2*>(&ws[kq * 4 + 0][2 * co]) = make_float2(v.x, v.x);
            *reinterpret_cast<float2*>(&ws[kq * 4 + 1][2 * co]) = make_float2(v.y, v.y);
            *reinterpret_cast<float2*>(&ws[kq * 4 + 2][2 * co]) = make_float2(v.z, v.z);
            *reinterpret_cast<float2*>(&ws[kq * 4 + 3][2 * co]) = make_float2(v.w, v.w);
        }
        __syncthreads();
#pragma unroll
        for (int kk = 0; kk < 16; kk++) {
            float4 xv = *reinterpret_cast<const float4*>(&xs[kk][lpx * 4]);
            float2 x0 = make_float2(xv.x, xv.y);
            float2 x1 = make_float2(xv.z, xv.w);
#pragma unroll
            for (int m = 0; m < 4; m++) {
                float4 wp = *reinterpret_cast<const float4*>(&ws[kk][cog * 16 + m * 4]);
                float2 wd0 = make_float2(wp.x, wp.y);
                float2 wd1 = make_float2(wp.z, wp.w);
                acc[2 * m + 0][0] = ffma2(x0, wd0, acc[2 * m + 0][0]);
                acc[2 * m + 0][1] = ffma2(x1, wd0, acc[2 * m + 0][1]);
                acc[2 * m + 1][0] = ffma2(x0, wd1, acc[2 * m + 1][0]);
                acc[2 * m + 1][1] = ffma2(x1, wd1, acc[2 * m + 1][1]);
            }
        }
        __syncthreads();
    }
#pragma unroll
    for (int j = 0; j < 8; j++) {
        int co = cobase + cog * 8 + j;
        float* ob = out + (size_t)(b * DIM + co) * HF * WF;
#pragma unroll
        for (int u = 0; u < 4; u++) {
            int p = px0 + lpx * 4 + u;
            int ii = p >> 7, jj = p & 127;
            float v = (u == 0) ? acc[j][0].x : (u == 1) ? acc[j][0].y
                    : (u == 2) ? acc[j][1].x : acc[j][1].y;
            float2 vv = make_float2(v, v);
            size_t o = (size_t)(2 * ii) * WF + 2 * jj;
            *reinterpret_cast<float2*>(&ob[o]) = vv;
            *reinterpret_cast<float2*>(&ob[o + WF]) = vv;
        }
    }
}

extern "C" void kernel_launch(void* const* d_in, const int* in_sizes, int n_in,
                              void* d_out, int out_size) {
    const float* x      = (const float*)d_in[0];
    const float* temp   = (const float*)d_in[1];
    const float* qkv_w  = (const float*)d_in[2];
    const float* dw_w   = (const float*)d_in[3];
    const float* proj_w = (const float*)d_in[4];
    const float* a1     = (const float*)d_in[5];
    const float* a2     = (const float*)d_in[6];
    const float* a3     = (const float*)d_in[7];
    const float* a4     = (const float*)d_in[8];
    float* out = (float*)d_out;

    k1_qkv_pool<<<dim3(4, 128, 36), 256>>>(x, qkv_w);
    k2_dw<<<dim3(128, 576, 4), 128>>>(dw_w);
    k_init<<<96, 256>>>();
    k4_gram<<<dim3(16, 6, 4), 256>>>();
    k5_softmax<<<24, 256>>>(temp, a1, a2, a3, a4);
    k6_apply<<<dim3(64, 24), 256>>>();
    k7_proj<<<dim3(128, 3, 4), 256>>>(proj_w, out);
}

// round 6
// speedup vs baseline: 1.9095x; 1.9095x over previous
#include <cuda_runtime.h>
#include <math.h>
#include <stdint.h>

#define BB 4
#define DIM 192
#define C3 576
#define HF 256
#define WF 256
#define HP 128
#define WP 128
#define NPX 16384
#define NHEADS 6
#define CPH 32

// scratch (device globals: allocation-free)
__device__ float g_P[BB * C3 * HP * WP];    // pooled qkv
__device__ float g_D[BB * C3 * HP * WP];    // after dwconv
__device__ float g_low[BB * DIM * NPX];     // gelu(out) low-res
__device__ float g_G[BB * NHEADS * CPH * CPH];
__device__ float g_A[BB * NHEADS * CPH * CPH];
__device__ float g_sq[BB * NHEADS * CPH];
__device__ float g_sk[BB * NHEADS * CPH];

__device__ __forceinline__ uint32_t to_tf32(float f) {
    uint32_t r;
    asm("cvt.rna.tf32.f32 %0, %1;" : "=r"(r) : "f"(f));
    return r;
}

__device__ __forceinline__ void mma_tf32(float* d, const uint32_t* a,
                                         uint32_t b0, uint32_t b1) {
    asm volatile(
        "mma.sync.aligned.m16n8k8.row.col.f32.tf32.tf32.f32 "
        "{%0,%1,%2,%3}, {%4,%5,%6,%7}, {%8,%9}, {%0,%1,%2,%3};"
        : "+f"(d[0]), "+f"(d[1]), "+f"(d[2]), "+f"(d[3])
        : "r"(a[0]), "r"(a[1]), "r"(a[2]), "r"(a[3]), "r"(b0), "r"(b1));
}

// ---------------------------------------------------------------------------
// K1: qkv 1x1 conv (GEMM W[576,192] @ X[192,N]) + fused 2x2 maxpool.
// CTA: 128 full-res px (= 32 pooled px, pooled-quad interleaved columns),
//      x tile RESIDENT in smem (read once), loops 9 co-tiles of 64.
// smem: Bs[192][136] tf32 (104448B), As[2][32][72] tf32 (18432B),
//       ps[64][36] f32 (9216B). Total 132096B.
// ---------------------------------------------------------------------------
#define K1_BS 0
#define K1_AS 104448
#define K1_PS (104448 + 18432)
#define K1_SMEM 132096

__global__ void __launch_bounds__(256) k1_mma(const float* __restrict__ x,
                                              const float* __restrict__ w) {
    extern __shared__ __align__(16) char smem[];
    uint32_t* Bs = (uint32_t*)(smem + K1_BS);   // [192][136]
    uint32_t* As = (uint32_t*)(smem + K1_AS);   // [2][32][72]
    float*    ps = (float*)(smem + K1_PS);      // [64][36]

    const int tid = threadIdx.x;
    const int ctaN = blockIdx.x;                // 0..511
    const int b = blockIdx.z;
    const int lane = tid & 31, warp = tid >> 5;
    const int warpM = warp >> 2, warpN = warp & 3;
    const int g = lane >> 2, t4 = lane & 3;

    const int pi = ctaN >> 2;                   // pooled row
    const int pj0 = (ctaN & 3) * 32;            // pooled col base

    // ---- resident B: 192k x 128n, pooled-quad interleaved, cvt tf32 ----
    {
        const float* xb = x + (size_t)b * DIM * (HF * WF)
                            + (size_t)(2 * pi) * WF + 2 * pj0;
        for (int idx = tid; idx < 192 * 64; idx += 256) {
            int kk = idx >> 6, rem = idx & 63;
            int r = rem >> 5, j = rem & 31;
            float2 v = *(const float2*)&xb[(size_t)kk * (HF * WF) + (size_t)r * WF + 2 * j];
            uint2 u = make_uint2(to_tf32(v.x), to_tf32(v.y));
            *(uint2*)&Bs[kk * 136 + 4 * j + 2 * r] = u;
        }
    }
    __syncthreads();

    const int coA = tid >> 2, kqA = tid & 3;    // A-load mapping

    for (int mt9 = 0; mt9 < 9; mt9++) {
        const int co0 = mt9 * 64;
        float acc[2][4][4];
#pragma unroll
        for (int i0 = 0; i0 < 2; i0++)
#pragma unroll
            for (int i1 = 0; i1 < 4; i1++)
#pragma unroll
                for (int i2 = 0; i2 < 4; i2++) acc[i0][i1][i2] = 0.f;

        const float* wbase = w + (size_t)(co0 + coA) * DIM + kqA * 4;
        // preload chunk 0 (32 k) into buf 0
        float4 ar0 = *(const float4*)(wbase);
        float4 ar1 = *(const float4*)(wbase + 16);
        {
            uint32_t* A0 = As;
            A0[(kqA * 4 + 0) * 72 + coA] = to_tf32(ar0.x);
            A0[(kqA * 4 + 1) * 72 + coA] = to_tf32(ar0.y);
            A0[(kqA * 4 + 2) * 72 + coA] = to_tf32(ar0.z);
            A0[(kqA * 4 + 3) * 72 + coA] = to_tf32(ar0.w);
            A0[(16 + kqA * 4 + 0) * 72 + coA] = to_tf32(ar1.x);
            A0[(16 + kqA * 4 + 1) * 72 + coA] = to_tf32(ar1.y);
            A0[(16 + kqA * 4 + 2) * 72 + coA] = to_tf32(ar1.z);
            A0[(16 + kqA * 4 + 3) * 72 + coA] = to_tf32(ar1.w);
        }
        __syncthreads();

        for (int c = 0; c < 6; c++) {
            const int bu = c & 1;
            if (c < 5) {
                ar0 = *(const float4*)(wbase + (c + 1) * 32);
                ar1 = *(const float4*)(wbase + (c + 1) * 32 + 16);
            }
            const uint32_t* A = As + bu * (32 * 72);
#pragma unroll
            for (int ks = 0; ks < 4; ks++) {
                const int kb = ks * 8;
                uint32_t a[2][4];
#pragma unroll
                for (int mt = 0; mt < 2; mt++) {
                    int m0 = warpM * 32 + mt * 16 + g;
                    a[mt][0] = A[(kb + t4) * 72 + m0];
                    a[mt][1] = A[(kb + t4) * 72 + m0 + 8];
                    a[mt][2] = A[(kb + t4 + 4) * 72 + m0];
                    a[mt][3] = A[(kb + t4 + 4) * 72 + m0 + 8];
                }
                const uint32_t* Bk = Bs + (c * 32 + kb) * 136;
#pragma unroll
                for (int nt = 0; nt < 4; nt++) {
                    int n0 = warpN * 32 + nt * 8 + g;
                    uint32_t b0 = Bk[t4 * 136 + n0];
                    uint32_t b1 = Bk[(t4 + 4) * 136 + n0];
                    mma_tf32(acc[0][nt], a[0], b0, b1);
                    mma_tf32(acc[1][nt], a[1], b0, b1);
                }
            }
            if (c < 5) {
                uint32_t* A2 = As + ((c + 1) & 1) * (32 * 72);
                A2[(kqA * 4 + 0) * 72 + coA] = to_tf32(ar0.x);
                A2[(kqA * 4 + 1) * 72 + coA] = to_tf32(ar0.y);
                A2[(kqA * 4 + 2) * 72 + coA] = to_tf32(ar0.z);
                A2[(kqA * 4 + 3) * 72 + coA] = to_tf32(ar0.w);
                A2[(16 + kqA * 4 + 0) * 72 + coA] = to_tf32(ar1.x);
                A2[(16 + kqA * 4 + 1) * 72 + coA] = to_tf32(ar1.y);
                A2[(16 + kqA * 4 + 2) * 72 + coA] = to_tf32(ar1.z);
                A2[(16 + kqA * 4 + 3) * 72 + coA] = to_tf32(ar1.w);
            }
            __syncthreads();
        }

        // epilogue: 2x2 pool (adjacent frag cols + shfl) -> stage -> store
#pragma unroll
        for (int mt = 0; mt < 2; mt++)
#pragma unroll
            for (int nt = 0; nt < 4; nt++) {
                float m01 = fmaxf(acc[mt][nt][0], acc[mt][nt][1]);
                float m23 = fmaxf(acc[mt][nt][2], acc[mt][nt][3]);
                m01 = fmaxf(m01, __shfl_xor_sync(0xffffffffu, m01, 1));
                m23 = fmaxf(m23, __shfl_xor_sync(0xffffffffu, m23, 1));
                if (!(t4 & 1)) {
                    int pj = warpN * 8 + nt * 2 + (t4 >> 1);
                    int co = warpM * 32 + mt * 16 + g;
                    ps[co * 36 + pj] = m01;
                    ps[(co + 8) * 36 + pj] = m23;
                }
            }
        __syncthreads();
        for (int idx = tid; idx < 64 * 8; idx += 256) {
            int row = idx >> 3, c4 = idx & 7;
            float4 v = *(const float4*)&ps[row * 36 + c4 * 4];
            *(float4*)&g_P[(((size_t)b * C3 + co0 + row) * HP + pi) * WP + pj0 + c4 * 4] = v;
        }
        __syncthreads();
    }
}

// ---------------------------------------------------------------------------
// K7: proj 1x1 conv at LOW-res (GEMM W[192,192] @ glow[192,N]) + nearest-x2
// duplicate epilogue into full-res out. Same resident-B structure, 3 co-tiles.
// smem: Bs[192][136] (104448B), As[2][32][72] (18432B), ps[64][132] (33792B).
// ---------------------------------------------------------------------------
#define K7_BS 0
#define K7_AS 104448
#define K7_PS (104448 + 18432)
#define K7_SMEM 156672

__global__ void __launch_bounds__(256) k7_mma(const float* __restrict__ w,
                                              float* __restrict__ out) {
    extern __shared__ __align__(16) char smem[];
    uint32_t* Bs = (uint32_t*)(smem + K7_BS);   // [192][136]
    uint32_t* As = (uint32_t*)(smem + K7_AS);   // [2][32][72]
    float*    ps = (float*)(smem + K7_PS);      // [64][132]

    const int tid = threadIdx.x;
    const int ctaN = blockIdx.x;                // low-res row 0..127
    const int b = blockIdx.z;
    const int lane = tid & 31, warp = tid >> 5;
    const int warpM = warp >> 2, warpN = warp & 3;
    const int g = lane >> 2, t4 = lane & 3;

    // resident B: 192k x 128 low-res px (one low-res row)
    {
        const float* xb = g_low + (size_t)b * DIM * NPX + (size_t)ctaN * 128;
        for (int idx = tid; idx < 192 * 64; idx += 256) {
            int kk = idx >> 6, j = idx & 63;
            float2 v = *(const float2*)&xb[(size_t)kk * NPX + 2 * j];
            uint2 u = make_uint2(to_tf32(v.x), to_tf32(v.y));
            *(uint2*)&Bs[kk * 136 + 2 * j] = u;
        }
    }
    __syncthreads();

    const int coA = tid >> 2, kqA = tid & 3;

    for (int mt3 = 0; mt3 < 3; mt3++) {
        const int co0 = mt3 * 64;
        float acc[2][4][4];
#pragma unroll
        for (int i0 = 0; i0 < 2; i0++)
#pragma unroll
            for (int i1 = 0; i1 < 4; i1++)
#pragma unroll
                for (int i2 = 0; i2 < 4; i2++) acc[i0][i1][i2] = 0.f;

        const float* wbase = w + (size_t)(co0 + coA) * DIM + kqA * 4;
        float4 ar0 = *(const float4*)(wbase);
        float4 ar1 = *(const float4*)(wbase + 16);
        {
            uint32_t* A0 = As;
            A0[(kqA * 4 + 0) * 72 + coA] = to_tf32(ar0.x);
            A0[(kqA * 4 + 1) * 72 + coA] = to_tf32(ar0.y);
            A0[(kqA * 4 + 2) * 72 + coA] = to_tf32(ar0.z);
            A0[(kqA * 4 + 3) * 72 + coA] = to_tf32(ar0.w);
            A0[(16 + kqA * 4 + 0) * 72 + coA] = to_tf32(ar1.x);
            A0[(16 + kqA * 4 + 1) * 72 + coA] = to_tf32(ar1.y);
            A0[(16 + kqA * 4 + 2) * 72 + coA] = to_tf32(ar1.z);
            A0[(16 + kqA * 4 + 3) * 72 + coA] = to_tf32(ar1.w);
        }
        __syncthreads();

        for (int c = 0; c < 6; c++) {
            const int bu = c & 1;
            if (c < 5) {
                ar0 = *(const float4*)(wbase + (c + 1) * 32);
                ar1 = *(const float4*)(wbase + (c + 1) * 32 + 16);
            }
            const uint32_t* A = As + bu * (32 * 72);
#pragma unroll
            for (int ks = 0; ks < 4; ks++) {
                const int kb = ks * 8;
                uint32_t a[2][4];
#pragma unroll
                for (int mt = 0; mt < 2; mt++) {
                    int m0 = warpM * 32 + mt * 16 + g;
                    a[mt][0] = A[(kb + t4) * 72 + m0];
                    a[mt][1] = A[(kb + t4) * 72 + m0 + 8];
                    a[mt][2] = A[(kb + t4 + 4) * 72 + m0];
                    a[mt][3] = A[(kb + t4 + 4) * 72 + m0 + 8];
                }
                const uint32_t* Bk = Bs + (c * 32 + kb) * 136;
#pragma unroll
                for (int nt = 0; nt < 4; nt++) {
                    int n0 = warpN * 32 + nt * 8 + g;
                    uint32_t b0 = Bk[t4 * 136 + n0];
                    uint32_t b1 = Bk[(t4 + 4) * 136 + n0];
                    mma_tf32(acc[0][nt], a[0], b0, b1);
                    mma_tf32(acc[1][nt], a[1], b0, b1);
                }
            }
            if (c < 5) {
                uint32_t* A2 = As + ((c + 1) & 1) * (32 * 72);
                A2[(kqA * 4 + 0) * 72 + coA] = to_tf32(ar0.x);
                A2[(kqA * 4 + 1) * 72 + coA] = to_tf32(ar0.y);
                A2[(kqA * 4 + 2) * 72 + coA] = to_tf32(ar0.z);
                A2[(kqA * 4 + 3) * 72 + coA] = to_tf32(ar0.w);
                A2[(16 + kqA * 4 + 0) * 72 + coA] = to_tf32(ar1.x);
                A2[(16 + kqA * 4 + 1) * 72 + coA] = to_tf32(ar1.y);
                A2[(16 + kqA * 4 + 2) * 72 + coA] = to_tf32(ar1.z);
                A2[(16 + kqA * 4 + 3) * 72 + coA] = to_tf32(ar1.w);
            }
            __syncthreads();
        }

        // stage full 64x128 tile
#pragma unroll
        for (int mt = 0; mt < 2; mt++)
#pragma unroll
            for (int nt = 0; nt < 4; nt++) {
                int co = warpM * 32 + mt * 16 + g;
                int n = warpN * 32 + nt * 8 + 2 * t4;
                *(float2*)&ps[co * 132 + n] = make_float2(acc[mt][nt][0], acc[mt][nt][1]);
                *(float2*)&ps[(co + 8) * 132 + n] = make_float2(acc[mt][nt][2], acc[mt][nt][3]);
            }
        __syncthreads();
        // duplicate-write to full res
        for (int idx = tid; idx < 64 * 32; idx += 256) {
            int row = idx >> 5, c4 = idx & 31;
            float4 s = *(const float4*)&ps[row * 132 + c4 * 4];
            float* ob = out + (size_t)(b * DIM + co0 + row) * (HF * WF)
                            + (size_t)(2 * ctaN) * WF + c4 * 8;
            float4 lo = make_float4(s.x, s.x, s.y, s.y);
            float4 hi = make_float4(s.z, s.z, s.w, s.w);
            *(float4*)(ob + 0) = lo;
            *(float4*)(ob + 4) = hi;
            *(float4*)(ob + WF) = lo;
            *(float4*)(ob + WF + 4) = hi;
        }
        __syncthreads();
    }
}

// ---------------------------------------------------------------------------
// K2: depthwise 3x3, SAME (zero pad), stride 1, on pooled grid.
// ---------------------------------------------------------------------------
__global__ void k2_dw(const float* __restrict__ dw) {
    int i = blockIdx.x, c = blockIdx.y, b = blockIdx.z;
    int j = threadIdx.x;  // 128
    __shared__ float s[3][130];
    const float* base = g_P + (size_t)(b * C3 + c) * HP * WP;
#pragma unroll
    for (int r = 0; r < 3; r++) {
        int ri = i + r - 1;
        s[r][j + 1] = (ri >= 0 && ri < HP) ? base[(size_t)ri * WP + j] : 0.f;
        if (j == 0) { s[r][0] = 0.f; s[r][129] = 0.f; }
    }
    __syncthreads();
    float acc = 0.f;
#pragma unroll
    for (int r = 0; r < 3; r++)
#pragma unroll
        for (int t = 0; t < 3; t++)
            acc = fmaf(dw[c * 9 + r * 3 + t], s[r][j + t], acc);
    g_D[((size_t)(b * C3 + c) * HP + i) * WP + j] = acc;
}

__global__ void k_init() {
    int idx = blockIdx.x * blockDim.x + threadIdx.x;
    if (idx < BB * NHEADS * CPH * CPH) g_G[idx] = 0.f;
    if (idx < BB * NHEADS * CPH) { g_sq[idx] = 0.f; g_sk[idx] = 0.f; }
}

// ---------------------------------------------------------------------------
// K4: gram matrix G = q @ k^T (raw) + per-row sum-of-squares for q, k.
// ---------------------------------------------------------------------------
__global__ void __launch_bounds__(256) k4_gram() {
    int s = blockIdx.x, h = blockIdx.y, b = blockIdx.z;
    int tid = threadIdx.x;
    __shared__ float qs[32][65];
    __shared__ float ks_[32][65];
    const float* qb = g_D + (size_t)(b * C3 + h * CPH) * NPX;
    const float* kb = g_D + (size_t)(b * C3 + DIM + h * CPH) * NPX;
    int row = tid >> 3;
    int cc = (tid & 7) * 8;
    int c = tid >> 3;
    int dbase = (tid & 7) * 4;
    float acc[4] = {0.f, 0.f, 0.f, 0.f};
    float sloc = 0.f;
    int n0 = s * 1024;
    for (int c0 = n0; c0 < n0 + 1024; c0 += 64) {
        float4 q0 = *reinterpret_cast<const float4*>(&qb[(size_t)row * NPX + c0 + cc]);
        float4 q1 = *reinterpret_cast<const float4*>(&qb[(size_t)row * NPX + c0 + cc + 4]);
        float4 k0v = *reinterpret_cast<const float4*>(&kb[(size_t)row * NPX + c0 + cc]);
        float4 k1v = *reinterpret_cast<const float4*>(&kb[(size_t)row * NPX + c0 + cc + 4]);
        qs[row][cc + 0] = q0.x; qs[row][cc + 1] = q0.y; qs[row][cc + 2] = q0.z; qs[row][cc + 3] = q0.w;
        qs[row][cc + 4] = q1.x; qs[row][cc + 5] = q1.y; qs[row][cc + 6] = q1.z; qs[row][cc + 7] = q1.w;
        ks_[row][cc + 0] = k0v.x; ks_[row][cc + 1] = k0v.y; ks_[row][cc + 2] = k0v.z; ks_[row][cc + 3] = k0v.w;
        ks_[row][cc + 4] = k1v.x; ks_[row][cc + 5] = k1v.y; ks_[row][cc + 6] = k1v.z; ks_[row][cc + 7] = k1v.w;
        __syncthreads();
#pragma unroll 4
        for (int kk = 0; kk < 64; kk++) {
            float qv = qs[c][kk];
#pragma unroll
            for (int j = 0; j < 4; j++) acc[j] = fmaf(qv, ks_[dbase + j][kk], acc[j]);
        }
        if (tid < 32) {
#pragma unroll 4
            for (int kk = 0; kk < 64; kk++) sloc = fmaf(qs[tid][kk], qs[tid][kk], sloc);
        } else if (tid < 64) {
#pragma unroll 4
            for (int kk = 0; kk < 64; kk++) sloc = fmaf(ks_[tid - 32][kk], ks_[tid - 32][kk], sloc);
        }
        __syncthreads();
    }
    int bh = b * NHEADS + h;
#pragma unroll
    for (int j = 0; j < 4; j++)
        atomicAdd(&g_G[((size_t)bh * CPH + c) * CPH + dbase + j], acc[j]);
    if (tid < 32) atomicAdd(&g_sq[bh * CPH + tid], sloc);
    else if (tid < 64) atomicAdd(&g_sk[bh * CPH + tid - 32], sloc);
}

// ---------------------------------------------------------------------------
// K5: normalize gram -> attn, 4 top-k masked softmaxes fused into combined A.
// ---------------------------------------------------------------------------
__global__ void k5_softmax(const float* __restrict__ temp,
                           const float* __restrict__ a1p, const float* __restrict__ a2p,
                           const float* __restrict__ a3p, const float* __restrict__ a4p) {
    int bh = blockIdx.x;
    int h = bh % NHEADS;
    int tid = threadIdx.x;
    int warp = tid >> 5, d = tid & 31;
    float t = temp[h];
    float A1 = *a1p, A2 = *a2p, A3 = *a3p, A4 = *a4p;
    float rk = 1.f / fmaxf(sqrtf(g_sk[bh * CPH + d]), 1e-12f);
    for (int it = 0; it < 4; it++) {
        int c = warp * 4 + it;
        float rq = 1.f / fmaxf(sqrtf(g_sq[bh * CPH + c]), 1e-12f);
        float v = g_G[((size_t)bh * CPH + c) * CPH + d] * rq * rk * t;
        int rank = 0;
#pragma unroll
        for (int j = 0; j < 32; j++) {
            float vj = __shfl_sync(0xffffffffu, v, j);
            rank += (vj > v) || (vj == v && j < d);
        }
        float vmax = v;
#pragma unroll
        for (int o = 16; o; o >>= 1) vmax = fmaxf(vmax, __shfl_xor_sync(0xffffffffu, vmax, o));
        float e = expf(v - vmax);
        float e1 = rank < 16 ? e : 0.f;
        float e2 = rank < 21 ? e : 0.f;
        float e3 = rank < 24 ? e : 0.f;
        float e4 = rank < 25 ? e : 0.f;
#pragma unroll
        for (int o = 16; o; o >>= 1) {
            e1 += __shfl_xor_sync(0xffffffffu, e1, o);
            e2 += __shfl_xor_sync(0xffffffffu, e2, o);
            e3 += __shfl_xor_sync(0xffffffffu, e3, o);
            e4 += __shfl_xor_sync(0xffffffffu, e4, o);
        }
        float wgt = (rank < 16 ? A1 / e1 : 0.f) + (rank < 21 ? A2 / e2 : 0.f)
                  + (rank < 24 ? A3 / e3 : 0.f) + (rank < 25 ? A4 / e4 : 0.f);
        g_A[((size_t)bh * CPH + c) * CPH + d] = e * wgt;
    }
}

// ---------------------------------------------------------------------------
// K6: out_low = A @ v, then exact GELU.
// ---------------------------------------------------------------------------
__global__ void __launch_bounds__(256) k6_apply() {
    int bh = blockIdx.y;
    int b = bh / NHEADS, h = bh % NHEADS;
    int tid = threadIdx.x;
    __shared__ float As[32][32];
    reinterpret_cast<float4*>(&As[0][0])[tid] =
        reinterpret_cast<const float4*>(&g_A[(size_t)bh * 1024])[tid];
    __syncthreads();
    int px = blockIdx.x * 256 + tid;
    const float* vb = g_D + (size_t)(b * C3 + 2 * DIM + h * CPH) * NPX + px;
    float acc[32];
#pragma unroll
    for (int c = 0; c < 32; c++) acc[c] = 0.f;
#pragma unroll 4
    for (int d = 0; d < 32; d++) {
        float vd = vb[(size_t)d * NPX];
#pragma unroll
        for (int c = 0; c < 32; c++) acc[c] = fmaf(As[c][d], vd, acc[c]);
    }
    float* ob = g_low + (size_t)(b * DIM + h * CPH) * NPX + px;
#pragma unroll
    for (int c = 0; c < 32; c++) {
        float xg = acc[c];
        ob[(size_t)c * NPX] = 0.5f * xg * (1.f + erff(xg * 0.70710678118654752f));
    }
}

extern "C" void kernel_launch(void* const* d_in, const int* in_sizes, int n_in,
                              void* d_out, int out_size) {
    const float* x      = (const float*)d_in[0];
    const float* temp   = (const float*)d_in[1];
    const float* qkv_w  = (const float*)d_in[2];
    const float* dw_w   = (const float*)d_in[3];
    const float* proj_w = (const float*)d_in[4];
    const float* a1     = (const float*)d_in[5];
    const float* a2     = (const float*)d_in[6];
    const float* a3     = (const float*)d_in[7];
    const float* a4     = (const float*)d_in[8];
    float* out = (float*)d_out;

    cudaFuncSetAttribute(k1_mma, cudaFuncAttributeMaxDynamicSharedMemorySize, K1_SMEM);
    cudaFuncSetAttribute(k7_mma, cudaFuncAttributeMaxDynamicSharedMemorySize, K7_SMEM);

    k1_mma<<<dim3(512, 1, 4), 256, K1_SMEM>>>(x, qkv_w);
    k2_dw<<<dim3(128, 576, 4), 128>>>(dw_w);
    k_init<<<96, 256>>>();
    k4_gram<<<dim3(16, 6, 4), 256>>>();
    k5_softmax<<<24, 256>>>(temp, a1, a2, a3, a4);
    k6_apply<<<dim3(64, 24), 256>>>();
    k7_mma<<<dim3(128, 1, 4), 256, K7_SMEM>>>(proj_w, out);
}

// round 7
// speedup vs baseline: 3.5983x; 1.8844x over previous
#include <cuda_runtime.h>
#include <cuda_fp16.h>
#include <math.h>
#include <stdint.h>

#define BB 4
#define DIM 192
#define C3 576
#define HF 256
#define WF 256
#define HP 128
#define WP 128
#define NPX 16384
#define NHEADS 6
#define CPH 32

// scratch (device globals: allocation-free)
__device__ float  g_P[BB * C3 * HP * WP];    // pooled qkv
__device__ float  g_D[BB * C3 * HP * WP];    // after dwconv
__device__ __half g_low[BB * DIM * NPX];     // gelu(out) low-res, fp16
__device__ float  g_G[BB * NHEADS * CPH * CPH];
__device__ float  g_A[BB * NHEADS * CPH * CPH];
__device__ float  g_sq[BB * NHEADS * CPH];
__device__ float  g_sk[BB * NHEADS * CPH];

// ============================ MMA helpers ==================================
__device__ __forceinline__ void mma_f16(float* d, const uint32_t* a, const uint32_t* b) {
    asm volatile(
        "mma.sync.aligned.m16n8k16.row.col.f32.f16.f16.f32 "
        "{%0,%1,%2,%3}, {%4,%5,%6,%7}, {%8,%9}, {%0,%1,%2,%3};"
        : "+f"(d[0]), "+f"(d[1]), "+f"(d[2]), "+f"(d[3])
        : "r"(a[0]), "r"(a[1]), "r"(a[2]), "r"(a[3]), "r"(b[0]), "r"(b[1]));
}
__device__ __forceinline__ void ldsm4(uint32_t* r, uint32_t a) {
    asm volatile("ldmatrix.sync.aligned.m8n8.x4.shared.b16 {%0,%1,%2,%3}, [%4];"
        : "=r"(r[0]), "=r"(r[1]), "=r"(r[2]), "=r"(r[3]) : "r"(a));
}
__device__ __forceinline__ void ldsm2t(uint32_t* r, uint32_t a) {
    asm volatile("ldmatrix.sync.aligned.m8n8.x2.trans.shared.b16 {%0,%1}, [%2];"
        : "=r"(r[0]), "=r"(r[1]) : "r"(a));
}
__device__ __forceinline__ uint32_t h2u(__half2 h) { return *(uint32_t*)&h; }

// ---------------------------------------------------------------------------
// K1: qkv 1x1 conv (W[576,192] @ X[192,128px]) fp16 MMA + fused 2x2 maxpool.
// B resident (x tile, k-major rows, pooled-quad interleaved n), 9 co-tiles.
// smem: Bs 192x136 fp16 (52224B) | As 2x64x40 fp16 (10240B) | ps 64x36 f32.
// ---------------------------------------------------------------------------
#define K1_A 52224
#define K1_P 62464
#define K1_SMEM 71680
#define BS_PAD 136   // fp16 per B row (272B, 16B-aligned)
#define AS_PAD 40    // fp16 per A row (80B)

__global__ void __launch_bounds__(256, 2) k1_mma(const float* __restrict__ x,
                                                 const float* __restrict__ w) {
    extern __shared__ __align__(16) char smem[];
    __half* Bs = (__half*)smem;
    __half* As = (__half*)(smem + K1_A);
    float*  ps = (float*)(smem + K1_P);
    uint32_t sbase;
    asm("{ .reg .u64 t; cvta.to.shared.u64 t, %1; cvt.u32.u64 %0, t; }"
        : "=r"(sbase) : "l"(smem));

    const int tid = threadIdx.x;
    const int ctaN = blockIdx.x, b = blockIdx.z;
    const int lane = tid & 31, warp = tid >> 5;
    const int warpM = warp >> 2, warpN = warp & 3;
    const int g = lane >> 2, t4 = lane & 3;

    const int pi = ctaN >> 2;
    const int pj0 = (ctaN & 3) * 32;

    // resident B: n = 4*j + 2*r + e (pooled-quad interleave), fp16
    {
        const float* xb = x + (size_t)b * DIM * (HF * WF)
                            + (size_t)(2 * pi) * WF + 2 * pj0;
        for (int idx = tid; idx < 192 * 64; idx += 256) {
            int kk = idx >> 6, rem = idx & 63;
            int r = rem >> 5, j = rem & 31;
            float2 v = *(const float2*)&xb[(size_t)kk * (HF * WF) + (size_t)r * WF + 2 * j];
            *(__half2*)&Bs[kk * BS_PAD + 4 * j + 2 * r] = __floats2half2_rn(v.x, v.y);
        }
    }

    // fragment smem addresses (invariant parts)
    const uint32_t aRow = sbase + K1_A
        + (uint32_t)(warpM * 32 + (lane & 15)) * 80 + ((lane >> 4) << 4);
    const uint32_t bRow = sbase
        + (uint32_t)((lane & 7) + (((lane >> 3) & 1) << 3)) * (BS_PAD * 2)
        + (uint32_t)(warpN * 32) * 2;

    const int coA = tid >> 2, kqA = tid & 3;
    __syncthreads();

    for (int mt9 = 0; mt9 < 9; mt9++) {
        const int co0 = mt9 * 64;
        float acc[2][4][4];
#pragma unroll
        for (int i0 = 0; i0 < 2; i0++)
#pragma unroll
            for (int i1 = 0; i1 < 4; i1++)
#pragma unroll
                for (int i2 = 0; i2 < 4; i2++) acc[i0][i1][i2] = 0.f;

        const float* wbase = w + (size_t)(co0 + coA) * DIM + kqA * 8;
        float4 w0 = *(const float4*)(wbase);
        float4 w1 = *(const float4*)(wbase + 4);
        {
            __half* A0 = As + coA * AS_PAD + kqA * 8;
            uint32_t u0 = h2u(__floats2half2_rn(w0.x, w0.y));
            uint32_t u1 = h2u(__floats2half2_rn(w0.z, w0.w));
            uint32_t u2 = h2u(__floats2half2_rn(w1.x, w1.y));
            uint32_t u3 = h2u(__floats2half2_rn(w1.z, w1.w));
            *(uint2*)(A0) = make_uint2(u0, u1);
            *(uint2*)(A0 + 4) = make_uint2(u2, u3);
        }
        __syncthreads();

        for (int c = 0; c < 6; c++) {
            const int bu = c & 1;
            if (c < 5) {
                w0 = *(const float4*)(wbase + (c + 1) * 32);
                w1 = *(const float4*)(wbase + (c + 1) * 32 + 4);
            }
            uint32_t afr[2][2][4], bfr[2][4][2];
            const uint32_t aB = aRow + bu * 5120;
            const uint32_t bB = bRow + (uint32_t)c * (32 * BS_PAD * 2);
#pragma unroll
            for (int ks = 0; ks < 2; ks++) {
#pragma unroll
                for (int mt = 0; mt < 2; mt++)
                    ldsm4(afr[ks][mt], aB + mt * (16 * 80) + ks * 32);
#pragma unroll
                for (int nt = 0; nt < 4; nt++)
                    ldsm2t(bfr[ks][nt], bB + ks * (16 * BS_PAD * 2) + nt * 16);
            }
#pragma unroll
            for (int ks = 0; ks < 2; ks++)
#pragma unroll
                for (int mt = 0; mt < 2; mt++)
#pragma unroll
                    for (int nt = 0; nt < 4; nt++)
                        mma_f16(acc[mt][nt], afr[ks][mt], bfr[ks][nt]);
            if (c < 5) {
                __half* A2 = As + ((c + 1) & 1) * 2560 + coA * AS_PAD + kqA * 8;
                uint32_t u0 = h2u(__floats2half2_rn(w0.x, w0.y));
                uint32_t u1 = h2u(__floats2half2_rn(w0.z, w0.w));
                uint32_t u2 = h2u(__floats2half2_rn(w1.x, w1.y));
                uint32_t u3 = h2u(__floats2half2_rn(w1.z, w1.w));
                *(uint2*)(A2) = make_uint2(u0, u1);
                *(uint2*)(A2 + 4) = make_uint2(u2, u3);
            }
            __syncthreads();
        }

        // epilogue: 2x2 pool (adjacent cols in-lane + shfl) -> stage -> store
#pragma unroll
        for (int mt = 0; mt < 2; mt++)
#pragma unroll
            for (int nt = 0; nt < 4; nt++) {
                float m01 = fmaxf(acc[mt][nt][0], acc[mt][nt][1]);
                float m23 = fmaxf(acc[mt][nt][2], acc[mt][nt][3]);
                m01 = fmaxf(m01, __shfl_xor_sync(0xffffffffu, m01, 1));
                m23 = fmaxf(m23, __shfl_xor_sync(0xffffffffu, m23, 1));
                if (!(t4 & 1)) {
                    int pj = warpN * 8 + nt * 2 + (t4 >> 1);
                    int co = warpM * 32 + mt * 16 + g;
                    ps[co * 36 + pj] = m01;
                    ps[(co + 8) * 36 + pj] = m23;
                }
            }
        __syncthreads();
        for (int idx = tid; idx < 64 * 8; idx += 256) {
            int row = idx >> 3, c4 = idx & 7;
            float4 v = *(const float4*)&ps[row * 36 + c4 * 4];
            *(float4*)&g_P[(((size_t)b * C3 + co0 + row) * HP + pi) * WP + pj0 + c4 * 4] = v;
        }
        __syncthreads();
    }
}

// ---------------------------------------------------------------------------
// K7: proj 1x1 conv at LOW-res fp16 MMA + nearest-x2 duplicate epilogue.
// smem: Bs 192x136 fp16 | As 2x64x40 fp16 | ps 64x132 f32 = 96256B total.
// ---------------------------------------------------------------------------
#define K7_A 52224
#define K7_P 62464
#define K7_SMEM 96256

__global__ void __launch_bounds__(256, 2) k7_mma(const float* __restrict__ w,
                                                 float* __restrict__ out) {
    extern __shared__ __align__(16) char smem[];
    __half* Bs = (__half*)smem;
    __half* As = (__half*)(smem + K7_A);
    float*  ps = (float*)(smem + K7_P);
    uint32_t sbase;
    asm("{ .reg .u64 t; cvta.to.shared.u64 t, %1; cvt.u32.u64 %0, t; }"
        : "=r"(sbase) : "l"(smem));

    const int tid = threadIdx.x;
    const int ctaN = blockIdx.x, b = blockIdx.z;   // low-res row
    const int lane = tid & 31, warp = tid >> 5;
    const int warpM = warp >> 2, warpN = warp & 3;
    const int g = lane >> 2, t4 = lane & 3;

    // resident B: one low-res row, 192k x 128px, fp16 passthrough
    {
        const __half* xb = g_low + (size_t)b * DIM * NPX + (size_t)ctaN * 128;
        for (int idx = tid; idx < 192 * 64; idx += 256) {
            int kk = idx >> 6, j = idx & 63;
            *(__half2*)&Bs[kk * BS_PAD + 2 * j] =
                *(const __half2*)&xb[(size_t)kk * NPX + 2 * j];
        }
    }

    const uint32_t aRow = sbase + K7_A
        + (uint32_t)(warpM * 32 + (lane & 15)) * 80 + ((lane >> 4) << 4);
    const uint32_t bRow = sbase
        + (uint32_t)((lane & 7) + (((lane >> 3) & 1) << 3)) * (BS_PAD * 2)
        + (uint32_t)(warpN * 32) * 2;

    const int coA = tid >> 2, kqA = tid & 3;
    __syncthreads();

    for (int mt3 = 0; mt3 < 3; mt3++) {
        const int co0 = mt3 * 64;
        float acc[2][4][4];
#pragma unroll
        for (int i0 = 0; i0 < 2; i0++)
#pragma unroll
            for (int i1 = 0; i1 < 4; i1++)
#pragma unroll
                for (int i2 = 0; i2 < 4; i2++) acc[i0][i1][i2] = 0.f;

        const float* wbase = w + (size_t)(co0 + coA) * DIM + kqA * 8;
        float4 w0 = *(const float4*)(wbase);
        float4 w1 = *(const float4*)(wbase + 4);
        {
            __half* A0 = As + coA * AS_PAD + kqA * 8;
            *(uint2*)(A0) = make_uint2(h2u(__floats2half2_rn(w0.x, w0.y)),
                                       h2u(__floats2half2_rn(w0.z, w0.w)));
            *(uint2*)(A0 + 4) = make_uint2(h2u(__floats2half2_rn(w1.x, w1.y)),
                                           h2u(__floats2half2_rn(w1.z, w1.w)));
        }
        __syncthreads();

        for (int c = 0; c < 6; c++) {
            const int bu = c & 1;
            if (c < 5) {
                w0 = *(const float4*)(wbase + (c + 1) * 32);
                w1 = *(const float4*)(wbase + (c + 1) * 32 + 4);
            }
            uint32_t afr[2][2][4], bfr[2][4][2];
            const uint32_t aB = aRow + bu * 5120;
            const uint32_t bB = bRow + (uint32_t)c * (32 * BS_PAD * 2);
#pragma unroll
            for (int ks = 0; ks < 2; ks++) {
#pragma unroll
                for (int mt = 0; mt < 2; mt++)
                    ldsm4(afr[ks][mt], aB + mt * (16 * 80) + ks * 32);
#pragma unroll
                for (int nt = 0; nt < 4; nt++)
                    ldsm2t(bfr[ks][nt], bB + ks * (16 * BS_PAD * 2) + nt * 16);
            }
#pragma unroll
            for (int ks = 0; ks < 2; ks++)
#pragma unroll
                for (int mt = 0; mt < 2; mt++)
#pragma unroll
                    for (int nt = 0; nt < 4; nt++)
                        mma_f16(acc[mt][nt], afr[ks][mt], bfr[ks][nt]);
            if (c < 5) {
                __half* A2 = As + ((c + 1) & 1) * 2560 + coA * AS_PAD + kqA * 8;
                *(uint2*)(A2) = make_uint2(h2u(__floats2half2_rn(w0.x, w0.y)),
                                           h2u(__floats2half2_rn(w0.z, w0.w)));
                *(uint2*)(A2 + 4) = make_uint2(h2u(__floats2half2_rn(w1.x, w1.y)),
                                               h2u(__floats2half2_rn(w1.z, w1.w)));
            }
            __syncthreads();
        }

        // stage full 64x128 tile, then duplicate-write to full res
#pragma unroll
        for (int mt = 0; mt < 2; mt++)
#pragma unroll
            for (int nt = 0; nt < 4; nt++) {
                int co = warpM * 32 + mt * 16 + g;
                int n = warpN * 32 + nt * 8 + 2 * t4;
                *(float2*)&ps[co * 132 + n] = make_float2(acc[mt][nt][0], acc[mt][nt][1]);
                *(float2*)&ps[(co + 8) * 132 + n] = make_float2(acc[mt][nt][2], acc[mt][nt][3]);
            }
        __syncthreads();
        for (int idx = tid; idx < 64 * 32; idx += 256) {
            int row = idx >> 5, c4 = idx & 31;
            float4 s = *(const float4*)&ps[row * 132 + c4 * 4];
            float* ob = out + (size_t)(b * DIM + co0 + row) * (HF * WF)
                            + (size_t)(2 * ctaN) * WF + c4 * 8;
            float4 lo = make_float4(s.x, s.x, s.y, s.y);
            float4 hi = make_float4(s.z, s.z, s.w, s.w);
            *(float4*)(ob + 0) = lo;
            *(float4*)(ob + 4) = hi;
            *(float4*)(ob + WF) = lo;
            *(float4*)(ob + WF + 4) = hi;
        }
        __syncthreads();
    }
}

// ---------------------------------------------------------------------------
// K2: depthwise 3x3, SAME, strip-mined: 32 output rows per block (halo 34).
// ---------------------------------------------------------------------------
__global__ void __launch_bounds__(256) k2_dw(const float* __restrict__ dw) {
    int strip = blockIdx.x, c = blockIdx.y, b = blockIdx.z;
    int i0 = strip * 32;
    int tid = threadIdx.x;
    __shared__ float s[34][132];
    const float* base = g_P + (size_t)(b * C3 + c) * HP * WP;
    for (int idx = tid; idx < 34 * 32; idx += 256) {
        int r = idx >> 5, c4 = idx & 31;
        int ri = i0 - 1 + r;
        float4 v = make_float4(0.f, 0.f, 0.f, 0.f);
        if (ri >= 0 && ri < HP) v = *(const float4*)&base[(size_t)ri * WP + c4 * 4];
        s[r][1 + c4 * 4 + 0] = v.x; s[r][1 + c4 * 4 + 1] = v.y;
        s[r][1 + c4 * 4 + 2] = v.z; s[r][1 + c4 * 4 + 3] = v.w;
    }
    if (tid < 34) { s[tid][0] = 0.f; s[tid][129] = 0.f; }
    __syncthreads();

    float k00 = dw[c * 9 + 0], k01 = dw[c * 9 + 1], k02 = dw[c * 9 + 2];
    float k10 = dw[c * 9 + 3], k11 = dw[c * 9 + 4], k12 = dw[c * 9 + 5];
    float k20 = dw[c * 9 + 6], k21 = dw[c * 9 + 7], k22 = dw[c * 9 + 8];

    int j = tid & 127;
    int r0 = (tid >> 7) * 16;
    float a0 = s[r0][j],     a1 = s[r0][j + 1],     a2 = s[r0][j + 2];
    float b0 = s[r0 + 1][j], b1 = s[r0 + 1][j + 1], b2 = s[r0 + 1][j + 2];
    float* ob = g_D + ((size_t)(b * C3 + c) * HP + i0 + r0) * WP + j;
#pragma unroll
    for (int r = 0; r < 16; r++) {
        float c0 = s[r0 + r + 2][j], c1 = s[r0 + r + 2][j + 1], c2 = s[r0 + r + 2][j + 2];
        float acc = k00 * a0;
        acc = fmaf(k01, a1, acc); acc = fmaf(k02, a2, acc);
        acc = fmaf(k10, b0, acc); acc = fmaf(k11, b1, acc); acc = fmaf(k12, b2, acc);
        acc = fmaf(k20, c0, acc); acc = fmaf(k21, c1, acc); acc = fmaf(k22, c2, acc);
        ob[(size_t)r * WP] = acc;
        a0 = b0; a1 = b1; a2 = b2;
        b0 = c0; b1 = c1; b2 = c2;
    }
}

__global__ void k_init() {
    int idx = blockIdx.x * blockDim.x + threadIdx.x;
    if (idx < BB * NHEADS * CPH * CPH) g_G[idx] = 0.f;
    if (idx < BB * NHEADS * CPH) { g_sq[idx] = 0.f; g_sk[idx] = 0.f; }
}

// ---------------------------------------------------------------------------
// K4: gram matrix + row sum-of-squares. 64 n-splits for occupancy.
// ---------------------------------------------------------------------------
__global__ void __launch_bounds__(256) k4_gram() {
    int s = blockIdx.x, h = blockIdx.y, b = blockIdx.z;
    int tid = threadIdx.x;
    __shared__ float qs[32][65];
    __shared__ float ks_[32][65];
    const float* qb = g_D + (size_t)(b * C3 + h * CPH) * NPX;
    const float* kb = g_D + (size_t)(b * C3 + DIM + h * CPH) * NPX;
    int row = tid >> 3;
    int cc = (tid & 7) * 8;
    int c = tid >> 3;
    int dbase = (tid & 7) * 4;
    float acc[4] = {0.f, 0.f, 0.f, 0.f};
    float sloc = 0.f;
    int n0 = s * 256;
    for (int c0 = n0; c0 < n0 + 256; c0 += 64) {
        float4 q0 = *reinterpret_cast<const float4*>(&qb[(size_t)row * NPX + c0 + cc]);
        float4 q1 = *reinterpret_cast<const float4*>(&qb[(size_t)row * NPX + c0 + cc + 4]);
        float4 k0v = *reinterpret_cast<const float4*>(&kb[(size_t)row * NPX + c0 + cc]);
        float4 k1v = *reinterpret_cast<const float4*>(&kb[(size_t)row * NPX + c0 + cc + 4]);
        qs[row][cc + 0] = q0.x; qs[row][cc + 1] = q0.y; qs[row][cc + 2] = q0.z; qs[row][cc + 3] = q0.w;
        qs[row][cc + 4] = q1.x; qs[row][cc + 5] = q1.y; qs[row][cc + 6] = q1.z; qs[row][cc + 7] = q1.w;
        ks_[row][cc + 0] = k0v.x; ks_[row][cc + 1] = k0v.y; ks_[row][cc + 2] = k0v.z; ks_[row][cc + 3] = k0v.w;
        ks_[row][cc + 4] = k1v.x; ks_[row][cc + 5] = k1v.y; ks_[row][cc + 6] = k1v.z; ks_[row][cc + 7] = k1v.w;
        __syncthreads();
#pragma unroll 4
        for (int kk = 0; kk < 64; kk++) {
            float qv = qs[c][kk];
#pragma unroll
            for (int j = 0; j < 4; j++) acc[j] = fmaf(qv, ks_[dbase + j][kk], acc[j]);
        }
        if (tid < 32) {
#pragma unroll 4
            for (int kk = 0; kk < 64; kk++) sloc = fmaf(qs[tid][kk], qs[tid][kk], sloc);
        } else if (tid < 64) {
#pragma unroll 4
            for (int kk = 0; kk < 64; kk++) sloc = fmaf(ks_[tid - 32][kk], ks_[tid - 32][kk], sloc);
        }
        __syncthreads();
    }
    int bh = b * NHEADS + h;
#pragma unroll
    for (int j = 0; j < 4; j++)
        atomicAdd(&g_G[((size_t)bh * CPH + c) * CPH + dbase + j], acc[j]);
    if (tid < 32) atomicAdd(&g_sq[bh * CPH + tid], sloc);
    else if (tid < 64) atomicAdd(&g_sk[bh * CPH + tid - 32], sloc);
}

// ---------------------------------------------------------------------------
// K5: normalize gram -> attn, 4 top-k masked softmaxes fused into combined A.
// ---------------------------------------------------------------------------
__global__ void k5_softmax(const float* __restrict__ temp,
                           const float* __restrict__ a1p, const float* __restrict__ a2p,
                           const float* __restrict__ a3p, const float* __restrict__ a4p) {
    int bh = blockIdx.x;
    int h = bh % NHEADS;
    int tid = threadIdx.x;
    int warp = tid >> 5, d = tid & 31;
    float t = temp[h];
    float A1 = *a1p, A2 = *a2p, A3 = *a3p, A4 = *a4p;
    float rk = 1.f / fmaxf(sqrtf(g_sk[bh * CPH + d]), 1e-12f);
    for (int it = 0; it < 4; it++) {
        int c = warp * 4 + it;
        float rq = 1.f / fmaxf(sqrtf(g_sq[bh * CPH + c]), 1e-12f);
        float v = g_G[((size_t)bh * CPH + c) * CPH + d] * rq * rk * t;
        int rank = 0;
#pragma unroll
        for (int j = 0; j < 32; j++) {
            float vj = __shfl_sync(0xffffffffu, v, j);
            rank += (vj > v) || (vj == v && j < d);
        }
        float vmax = v;
#pragma unroll
        for (int o = 16; o; o >>= 1) vmax = fmaxf(vmax, __shfl_xor_sync(0xffffffffu, vmax, o));
        float e = expf(v - vmax);
        float e1 = rank < 16 ? e : 0.f;
        float e2 = rank < 21 ? e : 0.f;
        float e3 = rank < 24 ? e : 0.f;
        float e4 = rank < 25 ? e : 0.f;
#pragma unroll
        for (int o = 16; o; o >>= 1) {
            e1 += __shfl_xor_sync(0xffffffffu, e1, o);
            e2 += __shfl_xor_sync(0xffffffffu, e2, o);
            e3 += __shfl_xor_sync(0xffffffffu, e3, o);
            e4 += __shfl_xor_sync(0xffffffffu, e4, o);
        }
        float wgt = (rank < 16 ? A1 / e1 : 0.f) + (rank < 21 ? A2 / e2 : 0.f)
                  + (rank < 24 ? A3 / e3 : 0.f) + (rank < 25 ? A4 / e4 : 0.f);
        g_A[((size_t)bh * CPH + c) * CPH + d] = e * wgt;
    }
}

// ---------------------------------------------------------------------------
// K6: out_low = A @ v, exact GELU, store fp16 (feeds fp16 GEMM in K7).
// ---------------------------------------------------------------------------
__global__ void __launch_bounds__(256) k6_apply() {
    int bh = blockIdx.y;
    int b = bh / NHEADS, h = bh % NHEADS;
    int tid = threadIdx.x;
    __shared__ float As[32][32];
    reinterpret_cast<float4*>(&As[0][0])[tid] =
        reinterpret_cast<const float4*>(&g_A[(size_t)bh * 1024])[tid];
    __syncthreads();
    int px = blockIdx.x * 256 + tid;
    const float* vb = g_D + (size_t)(b * C3 + 2 * DIM + h * CPH) * NPX + px;
    float acc[32];
#pragma unroll
    for (int c = 0; c < 32; c++) acc[c] = 0.f;
#pragma unroll 4
    for (int d = 0; d < 32; d++) {
        float vd = vb[(size_t)d * NPX];
#pragma unroll
        for (int c = 0; c < 32; c++) acc[c] = fmaf(As[c][d], vd, acc[c]);
    }
    __half* ob = g_low + (size_t)(b * DIM + h * CPH) * NPX + px;
#pragma unroll
    for (int c = 0; c < 32; c++) {
        float xg = acc[c];
        ob[(size_t)c * NPX] =
            __float2half_rn(0.5f * xg * (1.f + erff(xg * 0.70710678118654752f)));
    }
}

extern "C" void kernel_launch(void* const* d_in, const int* in_sizes, int n_in,
                              void* d_out, int out_size) {
    const float* x      = (const float*)d_in[0];
    const float* temp   = (const float*)d_in[1];
    const float* qkv_w  = (const float*)d_in[2];
    const float* dw_w   = (const float*)d_in[3];
    const float* proj_w = (const float*)d_in[4];
    const float* a1     = (const float*)d_in[5];
    const float* a2     = (const float*)d_in[6];
    const float* a3     = (const float*)d_in[7];
    const float* a4     = (const float*)d_in[8];
    float* out = (float*)d_out;

    cudaFuncSetAttribute(k1_mma, cudaFuncAttributeMaxDynamicSharedMemorySize, K1_SMEM);
    cudaFuncSetAttribute(k7_mma, cudaFuncAttributeMaxDynamicSharedMemorySize, K7_SMEM);

    k1_mma<<<dim3(512, 1, 4), 256, K1_SMEM>>>(x, qkv_w);
    k2_dw<<<dim3(4, 576, 4), 256>>>(dw_w);
    k_init<<<96, 256>>>();
    k4_gram<<<dim3(64, 6, 4), 256>>>();
    k5_softmax<<<24, 256>>>(temp, a1, a2, a3, a4);
    k6_apply<<<dim3(64, 24), 256>>>();
    k7_mma<<<dim3(128, 1, 4), 256, K7_SMEM>>>(proj_w, out);
}